// round 10
// baseline (speedup 1.0000x reference)
#include <cuda_runtime.h>
#include <cstdint>
#include <math_constants.h>

#define TOKENS  16384      // B*S
#define HDIM    4096
#define NEXP    64
#define MT      64         // tokens per CTA
#define KB      32         // k per stage
#define NST     (HDIM / KB)
#define NTHREADS 256       // 8 warps: 2 m-groups x 4 n-groups

#define A_STRIDE 36                       // floats per row (36 mod 32 = 4 -> conflict-free)
#define A_BYTES  (MT * A_STRIDE * 4)      // 9216
#define B_ROW    288                      // 36 uint2 per expert row (packed hi,lo)
#define B_BYTES  (NEXP * B_ROW)           // 18432
#define STG_BYTES (A_BYTES + B_BYTES)     // 27648
#define NBUF 3
#define SMEM_TOTAL (NBUF * STG_BYTES)     // 82944 per CTA; 2 CTAs/SM = 162KB

// loop-invariant: gate_w split to tf32 (hi,lo) once per launch
__device__ uint2 g_bsplit[NEXP * HDIM];   // 2MB static scratch

__device__ __forceinline__ void cp_async16(void* sdst, const void* gsrc) {
    uint32_t s = (uint32_t)__cvta_generic_to_shared(sdst);
    asm volatile("cp.async.cg.shared.global [%0], [%1], 16;\n"
                 :: "r"(s), "l"(gsrc) : "memory");
}
__device__ __forceinline__ void cp_commit() {
    asm volatile("cp.async.commit_group;\n" ::: "memory");
}
template <int N>
__device__ __forceinline__ void cp_wait() {
    asm volatile("cp.async.wait_group %0;\n" :: "n"(N) : "memory");
}

__device__ __forceinline__ void split_tf32(float v, uint32_t& hi, uint32_t& lo) {
    asm("cvt.rna.tf32.f32 %0, %1;" : "=r"(hi) : "f"(v));
    float l = v - __uint_as_float(hi);
    asm("cvt.rna.tf32.f32 %0, %1;" : "=r"(lo) : "f"(l));
}

__device__ __forceinline__ void mma_tf32(float* d, const uint32_t* a, const uint32_t* b) {
    asm volatile(
        "mma.sync.aligned.m16n8k8.row.col.f32.tf32.tf32.f32 "
        "{%0,%1,%2,%3}, {%4,%5,%6,%7}, {%8,%9}, {%0,%1,%2,%3};"
        : "+f"(d[0]), "+f"(d[1]), "+f"(d[2]), "+f"(d[3])
        : "r"(a[0]), "r"(a[1]), "r"(a[2]), "r"(a[3]), "r"(b[0]), "r"(b[1]));
}

// ---- pre-kernel: split gate_w once ----
__global__ __launch_bounds__(256)
void split_b_kernel(const float* __restrict__ w)
{
    int i = blockIdx.x * 256 + threadIdx.x;
#pragma unroll
    for (int p = 0; p < 4; p++) {
        int idx = i + p * (NEXP * HDIM / 4);
        uint32_t hi, lo;
        split_tf32(w[idx], hi, lo);
        g_bsplit[idx] = make_uint2(hi, lo);
    }
}

__global__ __launch_bounds__(NTHREADS, 2)
void molora_router_mma(const float* __restrict__ x,
                       float* __restrict__ out)
{
    extern __shared__ char smem[];
    const int tid  = threadIdx.x;
    const int wid  = tid >> 5;
    const int lane = tid & 31;
    const int wm   = wid & 1;   // m-group: m-tiles {2wm, 2wm+1}
    const int wn   = wid >> 1;  // n-group 0..3: experts wn*16 .. +15
    const int m0   = blockIdx.x * MT;

    const int row = lane >> 2;     // fragment row
    const int qk  = lane & 3;      // fragment k within half

    float d[2][2][4];
#pragma unroll
    for (int mi = 0; mi < 2; mi++)
#pragma unroll
        for (int ni = 0; ni < 2; ni++)
#pragma unroll
            for (int r = 0; r < 4; r++) d[mi][ni][r] = 0.0f;

    // ---- async fill of stage s into buffer buf ----
    auto fill = [&](int s, int buf) {
        char* Ab = smem + buf * STG_BYTES;
        char* Bb = Ab + A_BYTES;
        const int k0 = s * KB;
        // A: 64 tokens x 32 k fp32 -> 512 16B chunks, 2/thread
#pragma unroll
        for (int p = 0; p < 2; p++) {
            int q = tid + NTHREADS * p;
            int token = q >> 3, kq = q & 7;
            cp_async16(Ab + token * (A_STRIDE * 4) + kq * 16,
                       x + (size_t)(m0 + token) * HDIM + k0 + kq * 4);
        }
        // B packed: 64 exps x 32 uint2 -> 1024 16B chunks, 4/thread
#pragma unroll
        for (int p = 0; p < 4; p++) {
            int q = tid + NTHREADS * p;
            int exp = q >> 4, c = q & 15;   // 16 chunks per expert row
            cp_async16(Bb + exp * B_ROW + c * 16,
                       g_bsplit + (size_t)exp * HDIM + k0 + c * 2);
        }
        cp_commit();
    };

    // prologue: two stages in flight
    fill(0, 0);
    fill(1, 1);

    for (int s = 0; s < NST; s++) {
        const int buf = s % NBUF;
        if (s + 1 < NST) cp_wait<1>();
        else             cp_wait<0>();
        __syncthreads();   // single barrier per stage: also protects fill(s+2)
                           // overwriting buffer (s-1)%3, whose readers passed here

        const char* Ab = smem + buf * STG_BYTES;
        const float* Af = (const float*)Ab;
        const char* Bb = Ab + A_BYTES;

#pragma unroll
        for (int k8 = 0; k8 < 4; k8++) {
            const int col = k8 * 8 + qk;
            uint32_t ahi[2][4], alo[2][4];
#pragma unroll
            for (int mi = 0; mi < 2; mi++) {
                const int tb = (wm * 2 + mi) * 16 + row;
                float f0 = Af[tb * A_STRIDE + col];
                float f1 = Af[(tb + 8) * A_STRIDE + col];
                float f2 = Af[tb * A_STRIDE + col + 4];
                float f3 = Af[(tb + 8) * A_STRIDE + col + 4];
                split_tf32(f0, ahi[mi][0], alo[mi][0]);
                split_tf32(f1, ahi[mi][1], alo[mi][1]);
                split_tf32(f2, ahi[mi][2], alo[mi][2]);
                split_tf32(f3, ahi[mi][3], alo[mi][3]);
            }
            uint32_t bhi[2][2], blo[2][2];
#pragma unroll
            for (int ni = 0; ni < 2; ni++) {
                const int eb = (wn * 2 + ni) * 8 + row;
                uint2 g0 = *(const uint2*)(Bb + eb * B_ROW + col * 8);
                uint2 g1 = *(const uint2*)(Bb + eb * B_ROW + (col + 4) * 8);
                bhi[ni][0] = g0.x; blo[ni][0] = g0.y;
                bhi[ni][1] = g1.x; blo[ni][1] = g1.y;
            }
            // pass-major: 4 independent MMAs between accumulator reuse
#pragma unroll
            for (int mi = 0; mi < 2; mi++)
#pragma unroll
                for (int ni = 0; ni < 2; ni++)
                    mma_tf32(d[mi][ni], ahi[mi], bhi[ni]);
#pragma unroll
            for (int mi = 0; mi < 2; mi++)
#pragma unroll
                for (int ni = 0; ni < 2; ni++)
                    mma_tf32(d[mi][ni], ahi[mi], blo[ni]);
#pragma unroll
            for (int mi = 0; mi < 2; mi++)
#pragma unroll
                for (int ni = 0; ni < 2; ni++)
                    mma_tf32(d[mi][ni], alo[mi], bhi[ni]);
        }

        if (s + 2 < NST) fill(s + 2, (s + 2) % NBUF);
    }

    // ---- epilogue: per-warp top-2 over its 16 experts, then 4-way merge ----
    __syncthreads();
    float4* red = (float4*)smem;   // 64 tokens x 4 quarters x 16B = 4KB (buffers dead)

#pragma unroll
    for (int mi = 0; mi < 2; mi++) {
#pragma unroll
        for (int h = 0; h < 2; h++) {   // h=0: row, h=1: row+8
            float v1 = -CUDART_INF_F, v2 = -CUDART_INF_F;
            int i1 = 0, i2 = 0;
#pragma unroll
            for (int ni = 0; ni < 2; ni++)
#pragma unroll
                for (int r = 0; r < 2; r++) {
                    float v = d[mi][ni][h * 2 + r];
                    int   e = (wn * 2 + ni) * 8 + qk * 2 + r;
                    if (v > v1)      { v2 = v1; i2 = i1; v1 = v; i1 = e; }
                    else if (v > v2) { v2 = v;  i2 = e; }
                }
#pragma unroll
            for (int mk = 1; mk <= 2; mk <<= 1) {
                float ov1 = __shfl_xor_sync(0xffffffffu, v1, mk);
                float ov2 = __shfl_xor_sync(0xffffffffu, v2, mk);
                int   oi1 = __shfl_xor_sync(0xffffffffu, i1, mk);
                int   oi2 = __shfl_xor_sync(0xffffffffu, i2, mk);
                bool o1_beats_m1 = (ov1 > v1) || (ov1 == v1 && oi1 < i1);
                if (o1_beats_m1) {
                    bool m1_beats_o2 = (v1 > ov2) || (v1 == ov2 && i1 < oi2);
                    v2 = m1_beats_o2 ? v1 : ov2;
                    i2 = m1_beats_o2 ? i1 : oi2;
                    v1 = ov1; i1 = oi1;
                } else {
                    bool o1_beats_m2 = (ov1 > v2) || (ov1 == v2 && oi1 < i2);
                    if (o1_beats_m2) { v2 = ov1; i2 = oi1; }
                }
            }
            if (qk == 0) {
                int tok = (wm * 2 + mi) * 16 + row + h * 8;   // 0..63
                red[tok * 4 + wn] = make_float4(v1, v2, (float)i1, (float)i2);
            }
        }
    }
    __syncthreads();

    if (tid < MT) {
        // merge 4 descending pairs; quarters ordered by expert index,
        // ties prefer the earlier quarter (smaller index), per lax.top_k
        float4 c = red[tid * 4 + 0];
        float v1 = c.x, v2 = c.y;
        int   i1 = (int)c.z, i2 = (int)c.w;
#pragma unroll
        for (int q = 1; q < 4; q++) {
            float4 cq = red[tid * 4 + q];
            if (cq.x > v1) {
                if (v1 >= cq.y) { v2 = v1; i2 = i1; }
                else            { v2 = cq.y; i2 = (int)cq.w; }
                v1 = cq.x; i1 = (int)cq.z;
            } else if (cq.x > v2) {
                v2 = cq.x; i2 = (int)cq.z;
            }
        }
        float sfx = expf(v2 - v1);       // <= 1
        float inv = 1.0f / (1.0f + sfx);
        const int gt = m0 + tid;
        out[2 * gt + 0] = inv;
        out[2 * gt + 1] = sfx * inv;
        out[(size_t)TOKENS * 2 + 2 * gt + 0] = (float)i1;
        out[(size_t)TOKENS * 2 + 2 * gt + 1] = (float)i2;
    }
}

extern "C" void kernel_launch(void* const* d_in, const int* in_sizes, int n_in,
                              void* d_out, int out_size)
{
    const float* x = (const float*)d_in[0];      // [4,4096,4096] f32
    const float* w = (const float*)d_in[1];      // [64,4096]     f32
    float* out = (float*)d_out;

    (void)in_sizes; (void)n_in; (void)out_size;

    cudaFuncSetAttribute(molora_router_mma,
                         cudaFuncAttributeMaxDynamicSharedMemorySize, SMEM_TOTAL);

    // 1) split gate_w into tf32 hi/lo (loop-invariant, 2MB)
    split_b_kernel<<<NEXP * HDIM / 4 / 256, 256>>>(w);
    // 2) main GEMM + top-2 (256 CTAs, 2 per SM)
    molora_router_mma<<<TOKENS / MT, NTHREADS, SMEM_TOTAL>>>(x, out);
}

// round 11
// speedup vs baseline: 1.1140x; 1.1140x over previous
#include <cuda_runtime.h>
#include <cstdint>
#include <math_constants.h>

#define TOKENS  16384      // B*S
#define HDIM    4096
#define NEXP    64
#define MT      128        // tokens per CTA
#define KB      64         // k per stage
#define NST     (HDIM / KB)   // 64 stages
#define NK8     (KB / 8)      // 8
#define NTHREADS 256       // 8 warps: 4 m-groups x 2 n-groups

#define A_STRIDE 68                       // floats per row (68 mod 32 = 4 -> conflict-free)
#define A_BYTES  (MT * A_STRIDE * 4)      // 34816
#define B_BYTES  (NEXP * A_STRIDE * 4)    // 17408
#define STG_BYTES (A_BYTES + B_BYTES)     // 52224
#define NBUF 3
#define SMEM_TOTAL (NBUF * STG_BYTES)     // 156672

__device__ __forceinline__ void cp_async16(void* sdst, const void* gsrc) {
    uint32_t s = (uint32_t)__cvta_generic_to_shared(sdst);
    asm volatile("cp.async.cg.shared.global [%0], [%1], 16;\n"
                 :: "r"(s), "l"(gsrc) : "memory");
}
__device__ __forceinline__ void cp_commit() {
    asm volatile("cp.async.commit_group;\n" ::: "memory");
}
template <int N>
__device__ __forceinline__ void cp_wait() {
    asm volatile("cp.async.wait_group %0;\n" :: "n"(N) : "memory");
}

__device__ __forceinline__ void split_tf32(float v, uint32_t& hi, uint32_t& lo) {
    asm("cvt.rna.tf32.f32 %0, %1;" : "=r"(hi) : "f"(v));
    float l = v - __uint_as_float(hi);
    asm("cvt.rna.tf32.f32 %0, %1;" : "=r"(lo) : "f"(l));
}

__device__ __forceinline__ void mma_tf32(float* d, const uint32_t* a, const uint32_t* b) {
    asm volatile(
        "mma.sync.aligned.m16n8k8.row.col.f32.tf32.tf32.f32 "
        "{%0,%1,%2,%3}, {%4,%5,%6,%7}, {%8,%9}, {%0,%1,%2,%3};"
        : "+f"(d[0]), "+f"(d[1]), "+f"(d[2]), "+f"(d[3])
        : "r"(a[0]), "r"(a[1]), "r"(a[2]), "r"(a[3]), "r"(b[0]), "r"(b[1]));
}

__global__ __launch_bounds__(NTHREADS, 1)
void molora_router_mma(const float* __restrict__ x,
                       const float* __restrict__ w,
                       float* __restrict__ out)
{
    extern __shared__ char smem[];
    const int tid  = threadIdx.x;
    const int wid  = tid >> 5;
    const int lane = tid & 31;
    const int wm   = wid & 3;   // m-group: m-tiles {2wm, 2wm+1}
    const int wn   = wid >> 2;  // n-group: experts wn*32 .. +31
    const int m0   = blockIdx.x * MT;

    const int row = lane >> 2;     // fragment row
    const int qk  = lane & 3;      // fragment k within half

    float d[2][4][4];
#pragma unroll
    for (int mi = 0; mi < 2; mi++)
#pragma unroll
        for (int ni = 0; ni < 4; ni++)
#pragma unroll
            for (int r = 0; r < 4; r++) d[mi][ni][r] = 0.0f;

    // ---- async fill of stage s into buffer buf (KB=64: 12 chunks/thread) ----
    auto fill = [&](int s, int buf) {
        char* Ab = smem + buf * STG_BYTES;
        char* Bb = Ab + A_BYTES;
        const int k0 = s * KB;
        // A: 128 tokens x 16 chunks -> 2048 chunks, 8/thread
#pragma unroll
        for (int p = 0; p < 8; p++) {
            int q = tid + NTHREADS * p;
            int token = q >> 4, kq = q & 15;
            cp_async16(Ab + token * (A_STRIDE * 4) + kq * 16,
                       x + (size_t)(m0 + token) * HDIM + k0 + kq * 4);
        }
        // B: 64 experts x 16 chunks -> 1024 chunks, 4/thread
#pragma unroll
        for (int p = 0; p < 4; p++) {
            int q = tid + NTHREADS * p;
            int exp = q >> 4, kq = q & 15;
            cp_async16(Bb + exp * (A_STRIDE * 4) + kq * 16,
                       w + (size_t)exp * HDIM + k0 + kq * 4);
        }
        cp_commit();
    };

    // prologue: two stages in flight
    fill(0, 0);
    fill(1, 1);

    for (int s = 0; s < NST; s++) {
        const int buf = s % NBUF;
        if (s + 1 < NST) cp_wait<1>();
        else             cp_wait<0>();
        __syncthreads();   // single barrier per stage: also protects fill(s+2)
                           // overwriting buffer (s-1)%3, whose readers passed here

        const float* Af = (const float*)(smem + buf * STG_BYTES);
        const float* Bf = Af + MT * A_STRIDE;

#pragma unroll
        for (int k8 = 0; k8 < NK8; k8++) {
            const int col = k8 * 8 + qk;
            uint32_t ahi[2][4], alo[2][4];
#pragma unroll
            for (int mi = 0; mi < 2; mi++) {
                const int tb = (wm * 2 + mi) * 16 + row;
                float f0 = Af[tb * A_STRIDE + col];
                float f1 = Af[(tb + 8) * A_STRIDE + col];
                float f2 = Af[tb * A_STRIDE + col + 4];
                float f3 = Af[(tb + 8) * A_STRIDE + col + 4];
                split_tf32(f0, ahi[mi][0], alo[mi][0]);
                split_tf32(f1, ahi[mi][1], alo[mi][1]);
                split_tf32(f2, ahi[mi][2], alo[mi][2]);
                split_tf32(f3, ahi[mi][3], alo[mi][3]);
            }
            uint32_t bhi[4][2], blo[4][2];
#pragma unroll
            for (int ni = 0; ni < 4; ni++) {
                const int eb = (wn * 4 + ni) * 8 + row;
                float g0 = Bf[eb * A_STRIDE + col];
                float g1 = Bf[eb * A_STRIDE + col + 4];
                split_tf32(g0, bhi[ni][0], blo[ni][0]);
                split_tf32(g1, bhi[ni][1], blo[ni][1]);
            }
#pragma unroll
            for (int mi = 0; mi < 2; mi++)
#pragma unroll
                for (int ni = 0; ni < 4; ni++) {
                    mma_tf32(d[mi][ni], ahi[mi], bhi[ni]);
                    mma_tf32(d[mi][ni], ahi[mi], blo[ni]);
                    mma_tf32(d[mi][ni], alo[mi], bhi[ni]);
                }
        }

        if (s + 2 < NST) fill(s + 2, (s + 2) % NBUF);
    }

    // ---- epilogue: per-warp top-2 over its 32 experts, then cross-half merge ----
    __syncthreads();
    float4* red = (float4*)smem;   // 128 tokens x 2 halves x 16B = 4KB (buffers dead)

#pragma unroll
    for (int mi = 0; mi < 2; mi++) {
#pragma unroll
        for (int h = 0; h < 2; h++) {   // h=0: row, h=1: row+8
            float v1 = -CUDART_INF_F, v2 = -CUDART_INF_F;
            int i1 = 0, i2 = 0;
#pragma unroll
            for (int ni = 0; ni < 4; ni++)
#pragma unroll
                for (int r = 0; r < 2; r++) {
                    float v = d[mi][ni][h * 2 + r];
                    int   e = (wn * 4 + ni) * 8 + qk * 2 + r;
                    if (v > v1)      { v2 = v1; i2 = i1; v1 = v; i1 = e; }
                    else if (v > v2) { v2 = v;  i2 = e; }
                }
#pragma unroll
            for (int mk = 1; mk <= 2; mk <<= 1) {
                float ov1 = __shfl_xor_sync(0xffffffffu, v1, mk);
                float ov2 = __shfl_xor_sync(0xffffffffu, v2, mk);
                int   oi1 = __shfl_xor_sync(0xffffffffu, i1, mk);
                int   oi2 = __shfl_xor_sync(0xffffffffu, i2, mk);
                bool o1_beats_m1 = (ov1 > v1) || (ov1 == v1 && oi1 < i1);
                if (o1_beats_m1) {
                    bool m1_beats_o2 = (v1 > ov2) || (v1 == ov2 && i1 < oi2);
                    v2 = m1_beats_o2 ? v1 : ov2;
                    i2 = m1_beats_o2 ? i1 : oi2;
                    v1 = ov1; i1 = oi1;
                } else {
                    bool o1_beats_m2 = (ov1 > v2) || (ov1 == v2 && oi1 < i2);
                    if (o1_beats_m2) { v2 = ov1; i2 = oi1; }
                }
            }
            if (qk == 0) {
                int tok = (wm * 2 + mi) * 16 + row + h * 8;   // 0..127
                red[tok * 2 + wn] = make_float4(v1, v2, (float)i1, (float)i2);
            }
        }
    }
    __syncthreads();

    if (tid < MT) {
        float4 a = red[tid * 2 + 0];   // experts 0..31 (smaller indices)
        float4 b = red[tid * 2 + 1];   // experts 32..63
        float v1, v2; int i1, i2;
        if (a.x >= b.x) {
            v1 = a.x; i1 = (int)a.z;
            if (a.y >= b.x) { v2 = a.y; i2 = (int)a.w; }
            else            { v2 = b.x; i2 = (int)b.z; }
        } else {
            v1 = b.x; i1 = (int)b.z;
            if (a.x >= b.y) { v2 = a.x; i2 = (int)a.z; }
            else            { v2 = b.y; i2 = (int)b.w; }
        }
        float sfx = expf(v2 - v1);       // <= 1
        float inv = 1.0f / (1.0f + sfx);
        const int gt = m0 + tid;
        out[2 * gt + 0] = inv;
        out[2 * gt + 1] = sfx * inv;
        out[(size_t)TOKENS * 2 + 2 * gt + 0] = (float)i1;
        out[(size_t)TOKENS * 2 + 2 * gt + 1] = (float)i2;
    }
}

extern "C" void kernel_launch(void* const* d_in, const int* in_sizes, int n_in,
                              void* d_out, int out_size)
{
    const float* x = (const float*)d_in[0];      // [4,4096,4096] f32
    const float* w = (const float*)d_in[1];      // [64,4096]     f32
    float* out = (float*)d_out;

    (void)in_sizes; (void)n_in; (void)out_size;

    cudaFuncSetAttribute(molora_router_mma,
                         cudaFuncAttributeMaxDynamicSharedMemorySize, SMEM_TOTAL);

    dim3 grid(TOKENS / MT);   // 128 CTAs
    dim3 block(NTHREADS);
    molora_router_mma<<<grid, block, SMEM_TOTAL>>>(x, w, out);
}

// round 13
// speedup vs baseline: 2.0026x; 1.7977x over previous
#include <cuda_runtime.h>
#include <cuda_fp16.h>
#include <cstdint>
#include <math_constants.h>

#define TOKENS  16384      // B*S
#define HDIM    4096
#define NEXP    64
#define MT      128        // tokens per CTA
#define KB      64         // k per stage
#define NST     (HDIM / KB)   // 64 stages
#define NK16    (KB / 16)     // 4
#define NTHREADS 256       // 8 warps: 4 m-groups x 2 n-groups

// A: fp32, row stride 72 floats = 288B (>= 64 floats data; 36 float2 units, 36 mod 16 = 4 -> conflict-free LDS.64)
#define A_STRIDE 72
#define A_BYTES  (MT * A_STRIDE * 4)      // 36864
// B: packed half2 pairs {hi2, lo2} per 2 k-values; row stride 36 uint2 (36 mod 16 = 4)
#define B_ROW_U2 36
#define B_BYTES  (NEXP * B_ROW_U2 * 8)    // 18432
#define STG_BYTES (A_BYTES + B_BYTES)     // 55296
#define NBUF 3
#define SMEM_TOTAL (NBUF * STG_BYTES)     // 165888

// loop-invariant: gate_w split into fp16 (hi,lo) half2-pairs, once per launch (1MB)
__device__ uint2 g_bsplit[NEXP * HDIM / 2];

__device__ __forceinline__ void cp_async16(void* sdst, const void* gsrc) {
    uint32_t s = (uint32_t)__cvta_generic_to_shared(sdst);
    asm volatile("cp.async.cg.shared.global [%0], [%1], 16;\n"
                 :: "r"(s), "l"(gsrc) : "memory");
}
__device__ __forceinline__ void cp_commit() {
    asm volatile("cp.async.commit_group;\n" ::: "memory");
}
template <int N>
__device__ __forceinline__ void cp_wait() {
    asm volatile("cp.async.wait_group %0;\n" :: "n"(N) : "memory");
}

// split a pair of fp32 into packed half2 hi and half2 lo (3xFP16 decomposition)
__device__ __forceinline__ void split_f16x2(float a, float b, uint32_t& hi2, uint32_t& lo2) {
    half2 h = __floats2half2_rn(a, b);                  // low bits = a, high bits = b
    float ra = a - __half2float(__low2half(h));
    float rb = b - __half2float(__high2half(h));
    half2 l = __floats2half2_rn(ra, rb);
    hi2 = *(uint32_t*)&h;
    lo2 = *(uint32_t*)&l;
}

__device__ __forceinline__ void mma_f16(float* d, const uint32_t* a, const uint32_t* b) {
    asm volatile(
        "mma.sync.aligned.m16n8k16.row.col.f32.f16.f16.f32 "
        "{%0,%1,%2,%3}, {%4,%5,%6,%7}, {%8,%9}, {%0,%1,%2,%3};"
        : "+f"(d[0]), "+f"(d[1]), "+f"(d[2]), "+f"(d[3])
        : "r"(a[0]), "r"(a[1]), "r"(a[2]), "r"(a[3]), "r"(b[0]), "r"(b[1]));
}

// ---- pre-kernel: split gate_w once into packed half2 (hi,lo) per k-pair ----
__global__ __launch_bounds__(256)
void split_b_kernel(const float* __restrict__ w)
{
    int i = blockIdx.x * 256 + threadIdx.x;   // 32768 threads
#pragma unroll
    for (int p = 0; p < 4; p++) {
        int pair = i + p * 32768;             // 0 .. 131071
        float2 v = *(const float2*)(w + (size_t)pair * 2);
        uint32_t hi2, lo2;
        split_f16x2(v.x, v.y, hi2, lo2);
        g_bsplit[pair] = make_uint2(hi2, lo2);
    }
}

__global__ __launch_bounds__(NTHREADS, 1)
void molora_router_mma(const float* __restrict__ x,
                       float* __restrict__ out)
{
    extern __shared__ char smem[];
    const int tid  = threadIdx.x;
    const int wid  = tid >> 5;
    const int lane = tid & 31;
    const int wm   = wid & 3;   // m-group: m-tiles {2wm, 2wm+1}
    const int wn   = wid >> 2;  // n-group: experts wn*32 .. +31
    const int m0   = blockIdx.x * MT;

    const int row = lane >> 2;     // fragment row
    const int qk  = lane & 3;      // fragment k-pair within half

    float d[2][4][4];
#pragma unroll
    for (int mi = 0; mi < 2; mi++)
#pragma unroll
        for (int ni = 0; ni < 4; ni++)
#pragma unroll
            for (int r = 0; r < 4; r++) d[mi][ni][r] = 0.0f;

    // ---- async fill of stage s into buffer buf ----
    auto fill = [&](int s, int buf) {
        char* Ab = smem + buf * STG_BYTES;
        char* Bb = Ab + A_BYTES;
        const int k0 = s * KB;
        // A: 128 tokens x 16 chunks of 16B (64 floats) -> 2048 chunks, 8/thread
#pragma unroll
        for (int p = 0; p < 8; p++) {
            int q = tid + NTHREADS * p;
            int token = q >> 4, kq = q & 15;
            cp_async16(Ab + token * (A_STRIDE * 4) + kq * 16,
                       x + (size_t)(m0 + token) * HDIM + k0 + kq * 4);
        }
        // B: 64 experts x 16 chunks (32 uint2 = 256B used) -> 1024 chunks, 4/thread
#pragma unroll
        for (int p = 0; p < 4; p++) {
            int q = tid + NTHREADS * p;
            int exp = q >> 4, c = q & 15;
            cp_async16(Bb + exp * (B_ROW_U2 * 8) + c * 16,
                       g_bsplit + (size_t)exp * (HDIM / 2) + k0 / 2 + c * 2);
        }
        cp_commit();
    };

    // prologue: two stages in flight
    fill(0, 0);
    fill(1, 1);

    for (int s = 0; s < NST; s++) {
        const int buf = s % NBUF;
        if (s + 1 < NST) cp_wait<1>();
        else             cp_wait<0>();
        __syncthreads();   // single barrier/stage: fill(s+2) targets buffer (s-1)%3,
                           // whose readers all passed this barrier already

        const float* Af = (const float*)(smem + buf * STG_BYTES);
        const char*  Bb = (const char*)Af + A_BYTES;

#pragma unroll
        for (int k16 = 0; k16 < NK16; k16++) {
            // A fragments: fp32 pairs -> split to half2 in registers
            uint32_t ahi[2][4], alo[2][4];
#pragma unroll
            for (int mi = 0; mi < 2; mi++) {
                const int tb = (wm * 2 + mi) * 16 + row;
                const float2* r0 = (const float2*)(Af + tb * A_STRIDE) + k16 * 8 + qk;
                const float2* r1 = (const float2*)(Af + (tb + 8) * A_STRIDE) + k16 * 8 + qk;
                float2 p0 = r0[0];       // k = 2qk, 2qk+1
                float2 p1 = r1[0];
                float2 p2 = r0[4];       // k = 2qk+8, +9
                float2 p3 = r1[4];
                split_f16x2(p0.x, p0.y, ahi[mi][0], alo[mi][0]);
                split_f16x2(p1.x, p1.y, ahi[mi][1], alo[mi][1]);
                split_f16x2(p2.x, p2.y, ahi[mi][2], alo[mi][2]);
                split_f16x2(p3.x, p3.y, ahi[mi][3], alo[mi][3]);
            }
            // B fragments: preconverted packed {hi2, lo2} straight from smem
            uint32_t bhi[4][2], blo[4][2];
#pragma unroll
            for (int ni = 0; ni < 4; ni++) {
                const int eb = (wn * 4 + ni) * 8 + row;
                const uint2* Brow = (const uint2*)(Bb + eb * (B_ROW_U2 * 8));
                uint2 g0 = Brow[k16 * 8 + qk];       // k = 2qk, 2qk+1
                uint2 g1 = Brow[k16 * 8 + qk + 4];   // k = 2qk+8, +9
                bhi[ni][0] = g0.x; blo[ni][0] = g0.y;
                bhi[ni][1] = g1.x; blo[ni][1] = g1.y;
            }
            // pass-major: 8 independent MMAs between accumulator reuses
#pragma unroll
            for (int mi = 0; mi < 2; mi++)
#pragma unroll
                for (int ni = 0; ni < 4; ni++)
                    mma_f16(d[mi][ni], ahi[mi], bhi[ni]);
#pragma unroll
            for (int mi = 0; mi < 2; mi++)
#pragma unroll
                for (int ni = 0; ni < 4; ni++)
                    mma_f16(d[mi][ni], ahi[mi], blo[ni]);
#pragma unroll
            for (int mi = 0; mi < 2; mi++)
#pragma unroll
                for (int ni = 0; ni < 4; ni++)
                    mma_f16(d[mi][ni], alo[mi], bhi[ni]);
        }

        if (s + 2 < NST) fill(s + 2, (s + 2) % NBUF);
    }

    // ---- epilogue: per-warp top-2 over its 32 experts, then cross-half merge ----
    __syncthreads();
    float4* red = (float4*)smem;   // 128 tokens x 2 halves x 16B = 4KB (buffers dead)

#pragma unroll
    for (int mi = 0; mi < 2; mi++) {
#pragma unroll
        for (int h = 0; h < 2; h++) {   // h=0: row, h=1: row+8
            float v1 = -CUDART_INF_F, v2 = -CUDART_INF_F;
            int i1 = 0, i2 = 0;
#pragma unroll
            for (int ni = 0; ni < 4; ni++)
#pragma unroll
                for (int r = 0; r < 2; r++) {
                    float v = d[mi][ni][h * 2 + r];
                    int   e = (wn * 4 + ni) * 8 + qk * 2 + r;
                    if (v > v1)      { v2 = v1; i2 = i1; v1 = v; i1 = e; }
                    else if (v > v2) { v2 = v;  i2 = e; }
                }
#pragma unroll
            for (int mk = 1; mk <= 2; mk <<= 1) {
                float ov1 = __shfl_xor_sync(0xffffffffu, v1, mk);
                float ov2 = __shfl_xor_sync(0xffffffffu, v2, mk);
                int   oi1 = __shfl_xor_sync(0xffffffffu, i1, mk);
                int   oi2 = __shfl_xor_sync(0xffffffffu, i2, mk);
                bool o1_beats_m1 = (ov1 > v1) || (ov1 == v1 && oi1 < i1);
                if (o1_beats_m1) {
                    bool m1_beats_o2 = (v1 > ov2) || (v1 == ov2 && i1 < oi2);
                    v2 = m1_beats_o2 ? v1 : ov2;
                    i2 = m1_beats_o2 ? i1 : oi2;
                    v1 = ov1; i1 = oi1;
                } else {
                    bool o1_beats_m2 = (ov1 > v2) || (ov1 == v2 && oi1 < i2);
                    if (o1_beats_m2) { v2 = ov1; i2 = oi1; }
                }
            }
            if (qk == 0) {
                int tok = (wm * 2 + mi) * 16 + row + h * 8;   // 0..127
                red[tok * 2 + wn] = make_float4(v1, v2, (float)i1, (float)i2);
            }
        }
    }
    __syncthreads();

    if (tid < MT) {
        float4 a = red[tid * 2 + 0];   // experts 0..31 (smaller indices)
        float4 b = red[tid * 2 + 1];   // experts 32..63
        float v1, v2; int i1, i2;
        if (a.x >= b.x) {
            v1 = a.x; i1 = (int)a.z;
            if (a.y >= b.x) { v2 = a.y; i2 = (int)a.w; }
            else            { v2 = b.x; i2 = (int)b.z; }
        } else {
            v1 = b.x; i1 = (int)b.z;
            if (a.x >= b.y) { v2 = a.x; i2 = (int)a.z; }
            else            { v2 = b.y; i2 = (int)b.w; }
        }
        float sfx = expf(v2 - v1);       // <= 1
        float inv = 1.0f / (1.0f + sfx);
        const int gt = m0 + tid;
        out[2 * gt + 0] = inv;
        out[2 * gt + 1] = sfx * inv;
        out[(size_t)TOKENS * 2 + 2 * gt + 0] = (float)i1;
        out[(size_t)TOKENS * 2 + 2 * gt + 1] = (float)i2;
    }
}

extern "C" void kernel_launch(void* const* d_in, const int* in_sizes, int n_in,
                              void* d_out, int out_size)
{
    const float* x = (const float*)d_in[0];      // [4,4096,4096] f32
    const float* w = (const float*)d_in[1];      // [64,4096]     f32
    float* out = (float*)d_out;

    (void)in_sizes; (void)n_in; (void)out_size;

    cudaFuncSetAttribute(molora_router_mma,
                         cudaFuncAttributeMaxDynamicSharedMemorySize, SMEM_TOTAL);

    // 1) split gate_w into fp16 hi/lo packed pairs (loop-invariant, 1MB)
    split_b_kernel<<<128, 256>>>(w);
    // 2) main GEMM + top-2
    molora_router_mma<<<TOKENS / MT, NTHREADS, SMEM_TOTAL>>>(x, out);
}

// round 14
// speedup vs baseline: 2.3519x; 1.1744x over previous
#include <cuda_runtime.h>
#include <cuda_fp16.h>
#include <cstdint>
#include <math_constants.h>

#define TOKENS  16384      // B*S
#define HDIM    4096
#define NEXP    64
#define MT      128        // tokens per CTA
#define KB      32         // k per stage (per group)
#define KSPLIT  2          // two K-groups of 8 warps
#define KG      (HDIM / KSPLIT)   // 2048 k per group
#define NST     (KG / KB)         // 64 stages per group
#define NK16    (KB / 16)         // 2
#define NTHREADS 512       // 2 groups x 8 warps (4 m-groups x 2 n-groups each)

// A: fp32, row stride 40 floats = 160B (32 floats data; 20 float2 units, 20 mod 16 = 4 -> conflict-free LDS.64)
#define A_STRIDE 40
#define A_BYTES  (MT * A_STRIDE * 4)      // 20480
// B: packed half2 pairs {hi2,lo2}; row stride 20 uint2 = 160B (16 uint2 data; 20 mod 16 = 4)
#define B_ROW_U2 20
#define B_BYTES  (NEXP * B_ROW_U2 * 8)    // 10240
#define STG_BYTES (A_BYTES + B_BYTES)     // 30720
#define NBUF 3
#define GRP_BYTES (NBUF * STG_BYTES)      // 92160
#define SMEM_TOTAL (KSPLIT * GRP_BYTES)   // 184320

// loop-invariant: gate_w split into fp16 (hi,lo) half2-pairs, once per launch (1MB)
__device__ uint2 g_bsplit[NEXP * HDIM / 2];

__device__ __forceinline__ void cp_async16(void* sdst, const void* gsrc) {
    uint32_t s = (uint32_t)__cvta_generic_to_shared(sdst);
    asm volatile("cp.async.cg.shared.global [%0], [%1], 16;\n"
                 :: "r"(s), "l"(gsrc) : "memory");
}
__device__ __forceinline__ void cp_commit() {
    asm volatile("cp.async.commit_group;\n" ::: "memory");
}
template <int N>
__device__ __forceinline__ void cp_wait() {
    asm volatile("cp.async.wait_group %0;\n" :: "n"(N) : "memory");
}
__device__ __forceinline__ void bar_group(int g) {
    asm volatile("bar.sync %0, %1;" :: "r"(1 + g), "r"(256) : "memory");
}

// split a pair of fp32 into packed half2 hi and half2 lo (3xFP16 decomposition)
__device__ __forceinline__ void split_f16x2(float a, float b, uint32_t& hi2, uint32_t& lo2) {
    half2 h = __floats2half2_rn(a, b);
    float ra = a - __half2float(__low2half(h));
    float rb = b - __half2float(__high2half(h));
    half2 l = __floats2half2_rn(ra, rb);
    hi2 = *(uint32_t*)&h;
    lo2 = *(uint32_t*)&l;
}

__device__ __forceinline__ void mma_f16(float* d, const uint32_t* a, const uint32_t* b) {
    asm volatile(
        "mma.sync.aligned.m16n8k16.row.col.f32.f16.f16.f32 "
        "{%0,%1,%2,%3}, {%4,%5,%6,%7}, {%8,%9}, {%0,%1,%2,%3};"
        : "+f"(d[0]), "+f"(d[1]), "+f"(d[2]), "+f"(d[3])
        : "r"(a[0]), "r"(a[1]), "r"(a[2]), "r"(a[3]), "r"(b[0]), "r"(b[1]));
}

// ---- pre-kernel: split gate_w once into packed half2 (hi,lo) per k-pair ----
__global__ __launch_bounds__(256)
void split_b_kernel(const float* __restrict__ w)
{
    int i = blockIdx.x * 256 + threadIdx.x;
#pragma unroll
    for (int p = 0; p < 4; p++) {
        int pair = i + p * 32768;
        float2 v = *(const float2*)(w + (size_t)pair * 2);
        uint32_t hi2, lo2;
        split_f16x2(v.x, v.y, hi2, lo2);
        g_bsplit[pair] = make_uint2(hi2, lo2);
    }
}

__global__ __launch_bounds__(NTHREADS, 1)
void molora_router_mma(const float* __restrict__ x,
                       float* __restrict__ out)
{
    extern __shared__ char smem[];
    const int tid  = threadIdx.x;
    const int wid  = tid >> 5;
    const int lane = tid & 31;
    const int g    = wid >> 3;          // K-group 0/1
    const int wg   = wid & 7;           // warp within group
    const int wm   = wg & 3;            // m-group: m-tiles {2wm, 2wm+1}
    const int wn   = wg >> 2;           // n-group: experts wn*32 .. +31
    const int t256 = tid & 255;         // thread id within group
    const int m0   = blockIdx.x * MT;

    const int row = lane >> 2;
    const int qk  = lane & 3;

    char* gbase = smem + g * GRP_BYTES;

    float d[2][4][4];
#pragma unroll
    for (int mi = 0; mi < 2; mi++)
#pragma unroll
        for (int ni = 0; ni < 4; ni++)
#pragma unroll
            for (int r = 0; r < 4; r++) d[mi][ni][r] = 0.0f;

    // ---- async fill of group-local stage s into buffer buf ----
    auto fill = [&](int s, int buf) {
        char* Ab = gbase + buf * STG_BYTES;
        char* Bb = Ab + A_BYTES;
        const int k0 = g * KG + s * KB;
        // A: 128 tokens x 8 chunks of 16B -> 1024 chunks, 4/thread (group threads)
#pragma unroll
        for (int p = 0; p < 4; p++) {
            int q = t256 + 256 * p;
            int token = q >> 3, kq = q & 7;
            cp_async16(Ab + token * (A_STRIDE * 4) + kq * 16,
                       x + (size_t)(m0 + token) * HDIM + k0 + kq * 4);
        }
        // B: 64 experts x 8 chunks (16 uint2) -> 512 chunks, 2/thread
#pragma unroll
        for (int p = 0; p < 2; p++) {
            int q = t256 + 256 * p;
            int exp = q >> 3, c = q & 7;
            cp_async16(Bb + exp * (B_ROW_U2 * 8) + c * 16,
                       g_bsplit + (size_t)exp * (HDIM / 2) + k0 / 2 + c * 2);
        }
        cp_commit();
    };

    // prologue: two stages in flight (per group)
    fill(0, 0);
    fill(1, 1);

    for (int s = 0; s < NST; s++) {
        const int buf = s % NBUF;
        if (s + 1 < NST) cp_wait<1>();
        else             cp_wait<0>();
        bar_group(g);   // group-local barrier; also protects fill(s+2) overwriting
                        // buffer (s-1)%3, whose group readers passed here

        const float* Af = (const float*)(gbase + buf * STG_BYTES);
        const char*  Bb = (const char*)Af + A_BYTES;

#pragma unroll
        for (int k16 = 0; k16 < NK16; k16++) {
            uint32_t ahi[2][4], alo[2][4];
#pragma unroll
            for (int mi = 0; mi < 2; mi++) {
                const int tb = (wm * 2 + mi) * 16 + row;
                const float2* r0 = (const float2*)(Af + tb * A_STRIDE) + k16 * 8 + qk;
                const float2* r1 = (const float2*)(Af + (tb + 8) * A_STRIDE) + k16 * 8 + qk;
                float2 p0 = r0[0];
                float2 p1 = r1[0];
                float2 p2 = r0[4];
                float2 p3 = r1[4];
                split_f16x2(p0.x, p0.y, ahi[mi][0], alo[mi][0]);
                split_f16x2(p1.x, p1.y, ahi[mi][1], alo[mi][1]);
                split_f16x2(p2.x, p2.y, ahi[mi][2], alo[mi][2]);
                split_f16x2(p3.x, p3.y, ahi[mi][3], alo[mi][3]);
            }
            uint32_t bhi[4][2], blo[4][2];
#pragma unroll
            for (int ni = 0; ni < 4; ni++) {
                const int eb = (wn * 4 + ni) * 8 + row;
                const uint2* Brow = (const uint2*)(Bb + eb * (B_ROW_U2 * 8));
                uint2 g0 = Brow[k16 * 8 + qk];
                uint2 g1 = Brow[k16 * 8 + qk + 4];
                bhi[ni][0] = g0.x; blo[ni][0] = g0.y;
                bhi[ni][1] = g1.x; blo[ni][1] = g1.y;
            }
#pragma unroll
            for (int mi = 0; mi < 2; mi++)
#pragma unroll
                for (int ni = 0; ni < 4; ni++)
                    mma_f16(d[mi][ni], ahi[mi], bhi[ni]);
#pragma unroll
            for (int mi = 0; mi < 2; mi++)
#pragma unroll
                for (int ni = 0; ni < 4; ni++)
                    mma_f16(d[mi][ni], ahi[mi], blo[ni]);
#pragma unroll
            for (int mi = 0; mi < 2; mi++)
#pragma unroll
                for (int ni = 0; ni < 4; ni++)
                    mma_f16(d[mi][ni], alo[mi], bhi[ni]);
        }

        if (s + 2 < NST) fill(s + 2, (s + 2) % NBUF);
    }

    // ---- merge group 1's partial logits into group 0 ----
    __syncthreads();                       // all 512; buffers now dead
    float* Lx = (float*)smem;              // [128][68] partial logits, 34816B
    if (g == 1) {
#pragma unroll
        for (int mi = 0; mi < 2; mi++)
#pragma unroll
            for (int ni = 0; ni < 4; ni++)
#pragma unroll
                for (int h = 0; h < 2; h++) {
                    int tok = (wm * 2 + mi) * 16 + row + h * 8;
                    int col = wn * 32 + ni * 8 + qk * 2;
                    *(float2*)&Lx[tok * 68 + col] =
                        make_float2(d[mi][ni][h * 2], d[mi][ni][h * 2 + 1]);
                }
    }
    __syncthreads();
    float4* red = (float4*)(smem + 36864);   // 128 tokens x 2 halves x 16B

    if (g == 0) {
#pragma unroll
        for (int mi = 0; mi < 2; mi++)
#pragma unroll
            for (int ni = 0; ni < 4; ni++)
#pragma unroll
                for (int h = 0; h < 2; h++) {
                    int tok = (wm * 2 + mi) * 16 + row + h * 8;
                    int col = wn * 32 + ni * 8 + qk * 2;
                    float2 lv = *(const float2*)&Lx[tok * 68 + col];
                    d[mi][ni][h * 2]     += lv.x;
                    d[mi][ni][h * 2 + 1] += lv.y;
                }

        // per-warp top-2 over its 32 experts, quad reduce, publish candidates
#pragma unroll
        for (int mi = 0; mi < 2; mi++) {
#pragma unroll
            for (int h = 0; h < 2; h++) {
                float v1 = -CUDART_INF_F, v2 = -CUDART_INF_F;
                int i1 = 0, i2 = 0;
#pragma unroll
                for (int ni = 0; ni < 4; ni++)
#pragma unroll
                    for (int r = 0; r < 2; r++) {
                        float v = d[mi][ni][h * 2 + r];
                        int   e = (wn * 4 + ni) * 8 + qk * 2 + r;
                        if (v > v1)      { v2 = v1; i2 = i1; v1 = v; i1 = e; }
                        else if (v > v2) { v2 = v;  i2 = e; }
                    }
#pragma unroll
                for (int mk = 1; mk <= 2; mk <<= 1) {
                    float ov1 = __shfl_xor_sync(0xffffffffu, v1, mk);
                    float ov2 = __shfl_xor_sync(0xffffffffu, v2, mk);
                    int   oi1 = __shfl_xor_sync(0xffffffffu, i1, mk);
                    int   oi2 = __shfl_xor_sync(0xffffffffu, i2, mk);
                    bool o1_beats_m1 = (ov1 > v1) || (ov1 == v1 && oi1 < i1);
                    if (o1_beats_m1) {
                        bool m1_beats_o2 = (v1 > ov2) || (v1 == ov2 && i1 < oi2);
                        v2 = m1_beats_o2 ? v1 : ov2;
                        i2 = m1_beats_o2 ? i1 : oi2;
                        v1 = ov1; i1 = oi1;
                    } else {
                        bool o1_beats_m2 = (ov1 > v2) || (ov1 == v2 && oi1 < i2);
                        if (o1_beats_m2) { v2 = ov1; i2 = oi1; }
                    }
                }
                if (qk == 0) {
                    int tok = (wm * 2 + mi) * 16 + row + h * 8;
                    red[tok * 2 + wn] = make_float4(v1, v2, (float)i1, (float)i2);
                }
            }
        }
    }
    __syncthreads();

    if (tid < MT) {
        float4 a = red[tid * 2 + 0];   // experts 0..31 (smaller indices)
        float4 b = red[tid * 2 + 1];   // experts 32..63
        float v1, v2; int i1, i2;
        if (a.x >= b.x) {
            v1 = a.x; i1 = (int)a.z;
            if (a.y >= b.x) { v2 = a.y; i2 = (int)a.w; }
            else            { v2 = b.x; i2 = (int)b.z; }
        } else {
            v1 = b.x; i1 = (int)b.z;
            if (a.x >= b.y) { v2 = a.x; i2 = (int)a.z; }
            else            { v2 = b.y; i2 = (int)b.w; }
        }
        float sfx = expf(v2 - v1);       // <= 1
        float inv = 1.0f / (1.0f + sfx);
        const int gt = m0 + tid;
        out[2 * gt + 0] = inv;
        out[2 * gt + 1] = sfx * inv;
        out[(size_t)TOKENS * 2 + 2 * gt + 0] = (float)i1;
        out[(size_t)TOKENS * 2 + 2 * gt + 1] = (float)i2;
    }
}

extern "C" void kernel_launch(void* const* d_in, const int* in_sizes, int n_in,
                              void* d_out, int out_size)
{
    const float* x = (const float*)d_in[0];      // [4,4096,4096] f32
    const float* w = (const float*)d_in[1];      // [64,4096]     f32
    float* out = (float*)d_out;

    (void)in_sizes; (void)n_in; (void)out_size;

    cudaFuncSetAttribute(molora_router_mma,
                         cudaFuncAttributeMaxDynamicSharedMemorySize, SMEM_TOTAL);

    // 1) split gate_w into fp16 hi/lo packed pairs (loop-invariant, 1MB)
    split_b_kernel<<<128, 256>>>(w);
    // 2) main GEMM + top-2 (split-K x2 inside each CTA)
    molora_router_mma<<<TOKENS / MT, NTHREADS, SMEM_TOTAL>>>(x, out);
}